// round 11
// baseline (speedup 1.0000x reference)
#include <cuda_runtime.h>

// TorchGrouper — round 11: round-9 memory mappings + double-buffered tile.
// Software pipeline, ONE __syncthreads per g:
//   iter(g): LDG feats(g+NBLK) | voxel-prefetch(g+2NBLK) | drain tile[p]->g
//            | STS feats -> tile[1-p] | sync
// Output: [C,G,K] features, [4,G,K] gpf, [G] mask (float 1/0).

#define ZDIM 40
#define YDIM 400
#define XDIM 400
#define KK 64
#define CC 64
#define TPB 256
#define NBLK 1184        // 148 SMs x 8 launched (6 resident by smem)
#define TS 65            // tile row stride (floats)

__global__ __launch_bounds__(TPB, 6) void grouper_kernel(
    const int* __restrict__ vox,     // [N,Z,Y,X]
    const int* __restrict__ gpos,    // [G,4]
    const float* __restrict__ feat,  // [M,C]
    const int* __restrict__ off,     // [K,4]
    float* __restrict__ out,
    int G)
{
    __shared__ int      s_idx[2][KK];
    __shared__ unsigned s_ball[2][2];
    __shared__ float    s_tile[2][KK * TS];

    const int t    = threadIdx.x;
    const int w    = t >> 5;
    const int lane = t & 31;
    const size_t GK = (size_t)G * KK;
    float* out_gpf  = out + (size_t)CC * GK;
    float* out_mask = out + (size_t)(CC + 4) * GK;
    const float4* feat4 = reinterpret_cast<const float4*>(feat);

    // loop-invariant constants
    const int gpf_ch = t >> 6;
    const int gpf_k  = t & 63;
    const float gpf_val = (float)off[gpf_k * 4 + gpf_ch];
    int4 of = make_int4(0, 0, 0, 0);
    if (t < KK) of = reinterpret_cast<const int4*>(off)[t];

    // drain mapping (conflict-free, round 9): lane -> (ql, dc)
    const int ql = lane & 7;
    const int dc = lane >> 3;

    // ---- prologue ----
    const int g0 = blockIdx.x;
    if (t < KK) {
        // lookup g0 -> buffer 0
        {
            const int4 gp = reinterpret_cast<const int4*>(gpos)[g0];
            int z = min(max(gp.y + of.y, 0), ZDIM - 1);
            int y = min(max(gp.z + of.z, 0), YDIM - 1);
            int x = min(max(gp.w + of.w, 0), XDIM - 1);
            int idx = vox[((gp.x * ZDIM + z) * YDIM + y) * XDIM + x];
            s_idx[0][t] = idx;
            unsigned m = __ballot_sync(0xffffffffu, idx >= 0);
            if (lane == 0) s_ball[0][w] = m;
        }
        // lookup g0+NBLK -> buffer 1
        if (g0 + NBLK < G) {
            const int4 gp = reinterpret_cast<const int4*>(gpos)[g0 + NBLK];
            int z = min(max(gp.y + of.y, 0), ZDIM - 1);
            int y = min(max(gp.z + of.z, 0), YDIM - 1);
            int x = min(max(gp.w + of.w, 0), XDIM - 1);
            int idx = vox[((gp.x * ZDIM + z) * YDIM + y) * XDIM + x];
            s_idx[1][t] = idx;
            unsigned m = __ballot_sync(0xffffffffu, idx >= 0);
            if (lane == 0) s_ball[1][w] = m;
        }
    }
    __syncthreads();

    if (t == 0)
        out_mask[g0] = ((s_ball[0][0] | s_ball[0][1]) == 0u) ? 1.0f : 0.0f;

    // gather feats(g0) into tile[0]
#pragma unroll
    for (int j = 0; j < 4; j++) {
        const int job = t + TPB * j;
        const int k   = job >> 4;
        const int cq  = job & 15;
        const int idx = s_idx[0][k];
        float4 v = make_float4(0.f, 0.f, 0.f, 0.f);
        if (idx >= 0) v = feat4[(size_t)idx * (CC / 4) + cq];
        float* dst = &s_tile[0][k * TS + cq * 4];
        dst[0] = v.x; dst[1] = v.y; dst[2] = v.z; dst[3] = v.w;
    }
    __syncthreads();

    // ---- main pipelined loop: one barrier per g ----
    int p = 0, pi = 1;
    for (int g = g0; g < G; g += NBLK) {
        const int gn  = g + NBLK;
        const int gnn = g + 2 * NBLK;
        const bool hn = (gn < G);

        // (1) issue feature gathers for gn into registers (latency hidden by drain)
        float4 v0, v1, v2, v3;
        if (hn) {
            {
                const int k = t >> 4, cq = t & 15;
                const int idx = s_idx[pi][k];
                v0 = make_float4(0.f, 0.f, 0.f, 0.f);
                if (idx >= 0) v0 = feat4[(size_t)idx * (CC / 4) + cq];
            }
            {
                const int job = t + TPB; const int k = job >> 4, cq = job & 15;
                const int idx = s_idx[pi][k];
                v1 = make_float4(0.f, 0.f, 0.f, 0.f);
                if (idx >= 0) v1 = feat4[(size_t)idx * (CC / 4) + cq];
            }
            {
                const int job = t + 2 * TPB; const int k = job >> 4, cq = job & 15;
                const int idx = s_idx[pi][k];
                v2 = make_float4(0.f, 0.f, 0.f, 0.f);
                if (idx >= 0) v2 = feat4[(size_t)idx * (CC / 4) + cq];
            }
            {
                const int job = t + 3 * TPB; const int k = job >> 4, cq = job & 15;
                const int idx = s_idx[pi][k];
                v3 = make_float4(0.f, 0.f, 0.f, 0.f);
                if (idx >= 0) v3 = feat4[(size_t)idx * (CC / 4) + cq];
            }
            if (t == 0)
                out_mask[gn] = ((s_ball[pi][0] | s_ball[pi][1]) == 0u) ? 1.0f : 0.0f;
        }

        // (2) voxel prefetch for gnn -> s_idx[1-pi]
        if (t < KK && gnn < G) {
            const int4 gp = reinterpret_cast<const int4*>(gpos)[gnn];
            int z = min(max(gp.y + of.y, 0), ZDIM - 1);
            int y = min(max(gp.z + of.z, 0), YDIM - 1);
            int x = min(max(gp.w + of.w, 0), XDIM - 1);
            int idx = vox[((gp.x * ZDIM + z) * YDIM + y) * XDIM + x];
            s_idx[1 - pi][t] = idx;
            unsigned m = __ballot_sync(0xffffffffu, idx >= 0);
            if (lane == 0) s_ball[1 - pi][w] = m;
        }

        // (3) drain tile[p] -> out[g]  (CF LDS + streaming STG.128)
#pragma unroll
        for (int j = 0; j < 4; j++) {
            const int task = w * 4 + j;
            const int c0   = (task & 15) * 4;
            const int qh   = task >> 4;
            const int q    = qh * 8 + ql;
            const int c    = c0 + dc;
            float4 o;
            o.x = s_tile[p][(q * 4 + 0) * TS + c];
            o.y = s_tile[p][(q * 4 + 1) * TS + c];
            o.z = s_tile[p][(q * 4 + 2) * TS + c];
            o.w = s_tile[p][(q * 4 + 3) * TS + c];
            __stcs(reinterpret_cast<float4*>(
                       out + (size_t)c * GK + (size_t)g * KK + q * 4), o);
        }

        // gpf for g
        __stcs(out_gpf + (size_t)gpf_ch * GK + (size_t)g * KK + gpf_k, gpf_val);

        // (4) STS gathered feats -> tile[1-p]
        if (hn) {
            float* base = s_tile[1 - p];
            {
                const int k = t >> 4, cq = t & 15;
                float* dst = &base[k * TS + cq * 4];
                dst[0] = v0.x; dst[1] = v0.y; dst[2] = v0.z; dst[3] = v0.w;
            }
            {
                const int job = t + TPB; const int k = job >> 4, cq = job & 15;
                float* dst = &base[k * TS + cq * 4];
                dst[0] = v1.x; dst[1] = v1.y; dst[2] = v1.z; dst[3] = v1.w;
            }
            {
                const int job = t + 2 * TPB; const int k = job >> 4, cq = job & 15;
                float* dst = &base[k * TS + cq * 4];
                dst[0] = v2.x; dst[1] = v2.y; dst[2] = v2.z; dst[3] = v2.w;
            }
            {
                const int job = t + 3 * TPB; const int k = job >> 4, cq = job & 15;
                float* dst = &base[k * TS + cq * 4];
                dst[0] = v3.x; dst[1] = v3.y; dst[2] = v3.z; dst[3] = v3.w;
            }
        }

        __syncthreads();
        p ^= 1; pi ^= 1;
    }
}

extern "C" void kernel_launch(void* const* d_in, const int* in_sizes, int n_in,
                              void* d_out, int out_size) {
    const int*   vox  = (const int*)d_in[0];
    const int*   gpos = (const int*)d_in[1];
    const float* feat = (const float*)d_in[2];
    const int*   off  = (const int*)d_in[3];
    float* out = (float*)d_out;

    const int G = in_sizes[1] / 4;   // 30000
    grouper_kernel<<<NBLK, TPB>>>(vox, gpos, feat, off, out, G);
}

// round 12
// speedup vs baseline: 1.3854x; 1.3854x over previous
#include <cuda_runtime.h>

// TorchGrouper — round 12: round-9 pipeline, but the feature gather uses
// cp.async.cg (16B, zero-fill via src-size) into an XOR-swizzled float4
// tile: slot(k,cq) -> k*16 + (cq ^ (k>>2 & 15)). Removes all gather STS
// wavefronts and the LDG->STS register dependency. Drain LDS verified
// conflict-free: bank = 16r + 4*((cq0^q)&7) + dc -> 32 distinct.
// Output: [C,G,K] features, [4,G,K] gpf, [G] mask (float 1/0).

#define ZDIM 40
#define YDIM 400
#define XDIM 400
#define KK 64
#define CC 64
#define TPB 256
#define NBLK 1184        // 148 SMs x 8 resident blocks

__global__ __launch_bounds__(TPB, 8) void grouper_kernel(
    const int* __restrict__ vox,     // [N,Z,Y,X]
    const int* __restrict__ gpos,    // [G,4]
    const float* __restrict__ feat,  // [M,C]
    const int* __restrict__ off,     // [K,4]
    float* __restrict__ out,
    int G)
{
    __shared__ int      s_idx[2][KK];
    __shared__ unsigned s_ball[2][2];
    __shared__ float4   s_tile[KK * 16];   // XOR-swizzled [k][cq'], 16 KB

    const int t    = threadIdx.x;
    const int w    = t >> 5;
    const int lane = t & 31;
    const size_t GK = (size_t)G * KK;
    float* out_gpf  = out + (size_t)CC * GK;
    float* out_mask = out + (size_t)(CC + 4) * GK;
    const float* tf = reinterpret_cast<const float*>(s_tile);
    const unsigned tile_smem =
        (unsigned)__cvta_generic_to_shared(s_tile);

    // loop-invariant constants
    const int gpf_ch = t >> 6;
    const int gpf_k  = t & 63;
    const float gpf_val = (float)off[gpf_k * 4 + gpf_ch];
    int4 of = make_int4(0, 0, 0, 0);
    if (t < KK) of = reinterpret_cast<const int4*>(off)[t];

    // drain mapping (conflict-free): lane -> (ql, dc)
    const int ql = lane & 7;
    const int dc = lane >> 3;

    // gather job constants (job = t + 256*j): k = job>>4, cq = job&15
    // ---- prologue: lookup for first g ----
    int g = blockIdx.x;
    if (t < KK) {
        const int4 gp = reinterpret_cast<const int4*>(gpos)[g];
        int z = min(max(gp.y + of.y, 0), ZDIM - 1);
        int y = min(max(gp.z + of.z, 0), YDIM - 1);
        int x = min(max(gp.w + of.w, 0), XDIM - 1);
        int idx = vox[((gp.x * ZDIM + z) * YDIM + y) * XDIM + x];
        s_idx[0][t] = idx;
        unsigned m = __ballot_sync(0xffffffffu, idx >= 0);
        if (lane == 0) s_ball[0][w] = m;
    }
    __syncthreads();

    int p = 0;
    for (; g < G; g += NBLK) {
        const int g_next = g + NBLK;
        const bool has_next = (g_next < G);

        // ---- prefetch next g's voxel lookups into registers ----
        int idxnext = -1;
        if (t < KK && has_next) {
            const int4 gp = reinterpret_cast<const int4*>(gpos)[g_next];
            int z = min(max(gp.y + of.y, 0), ZDIM - 1);
            int y = min(max(gp.z + of.z, 0), YDIM - 1);
            int x = min(max(gp.w + of.w, 0), XDIM - 1);
            idxnext = vox[((gp.x * ZDIM + z) * YDIM + y) * XDIM + x];
        }

        // ---- gather current g via cp.async (zero-fill when idx < 0) ----
#pragma unroll
        for (int j = 0; j < 4; j++) {
            const int job = t + TPB * j;     // 0..1023
            const int k   = job >> 4;        // 0..63
            const int cq  = job & 15;
            const int idx = s_idx[p][k];
            const int slot = k * 16 + (cq ^ ((k >> 2) & 15));
            const unsigned dst = tile_smem + slot * 16;
            const float* src = feat + (size_t)max(idx, 0) * CC + cq * 4;
            const int srcsz = (idx >= 0) ? 16 : 0;
            asm volatile(
                "cp.async.cg.shared.global [%0], [%1], 16, %2;"
                :: "r"(dst), "l"(src), "r"(srcsz));
        }
        asm volatile("cp.async.commit_group;");
        asm volatile("cp.async.wait_group 0;");
        __syncthreads();

        // ---- drain: transposed float4 streaming stores, CF LDS ----
#pragma unroll
        for (int j = 0; j < 4; j++) {
            const int task = w * 4 + j;              // 0..31
            const int c0   = (task & 15) * 4;        // 0..60
            const int qh   = task >> 4;              // 0..1
            const int q    = qh * 8 + ql;            // 0..15
            const int c    = c0 + dc;
            const int cq0  = c0 >> 2;
            float4 v;
            v.x = tf[((q * 4 + 0) * 16 + (cq0 ^ (q & 15))) * 4 + dc];
            v.y = tf[((q * 4 + 1) * 16 + (cq0 ^ (q & 15))) * 4 + dc];
            v.z = tf[((q * 4 + 2) * 16 + (cq0 ^ (q & 15))) * 4 + dc];
            v.w = tf[((q * 4 + 3) * 16 + (cq0 ^ (q & 15))) * 4 + dc];
            __stcs(reinterpret_cast<float4*>(
                       out + (size_t)c * GK + (size_t)g * KK + q * 4), v);
        }

        // ---- gpf + mask for current g ----
        __stcs(out_gpf + (size_t)gpf_ch * GK + (size_t)g * KK + gpf_k, gpf_val);
        if (t == 0)
            out_mask[g] = ((s_ball[p][0] | s_ball[p][1]) == 0u) ? 1.0f : 0.0f;

        // ---- publish prefetched lookups into the other buffer ----
        if (t < KK && has_next) {
            s_idx[1 - p][t] = idxnext;
            unsigned m = __ballot_sync(0xffffffffu, idxnext >= 0);
            if (lane == 0) s_ball[1 - p][w] = m;
        }
        __syncthreads();
        p ^= 1;
    }
}

extern "C" void kernel_launch(void* const* d_in, const int* in_sizes, int n_in,
                              void* d_out, int out_size) {
    const int*   vox  = (const int*)d_in[0];
    const int*   gpos = (const int*)d_in[1];
    const float* feat = (const float*)d_in[2];
    const int*   off  = (const int*)d_in[3];
    float* out = (float*)d_out;

    const int G = in_sizes[1] / 4;   // 30000
    grouper_kernel<<<NBLK, TPB>>>(vox, gpos, feat, off, out, G);
}